// round 6
// baseline (speedup 1.0000x reference)
#include <cuda_runtime.h>
#include <math.h>

#define FEAT 128
#define HID  64
#define NMAX 50048
#define EMAX 1048576

// ---------------- scratch (static __device__, zero-initialized at load) ----------------
__device__ float g_h[NMAX * FEAT];      // post-GEMM features h
__device__ float g_y[NMAX * HID];       // post-epilogue features
__device__ float g_agg[NMAX * FEAT];    // edge-aggregated output (invariant: zero between runs)
__device__ float g_as[NMAX];            // alpha_src per node
__device__ float g_ad[NMAX];            // alpha_dst per node
__device__ float g_s[NMAX];             // segment sum
__device__ float g_e[EMAX];             // per-edge exp(e)
__device__ int2  g_sd[EMAX];            // packed (src, dst)
__device__ float g_colsum[4 * FEAT];    // per-layer BN stat slots
__device__ float g_colsq[4 * FEAT];
__device__ int   g_is64;

// ---------------- startup: zero BN stat slots + detect index dtype ----------------
__global__ void start_kernel(const void* ei) {
    int t = threadIdx.x;
    if (t < 4 * FEAT) { g_colsum[t] = 0.f; g_colsq[t] = 0.f; }
    if (t < 32) {
        const long long* p = (const long long*)ei;
        int bad = 0;
        for (int i = t; i < 64; i += 32) {
            long long v = p[i];
            if (v < 0 || v >= (1LL << 31)) bad = 1;
        }
        bad = __any_sync(0xffffffffu, bad);
        if (t == 0) g_is64 = bad ? 0 : 1;
    }
}

__global__ void convert_kernel(const void* ei, int E, int ET) {
    int i = blockIdx.x * blockDim.x + threadIdx.x;
    if (i >= ET) return;
    if (i < E) {
        if (g_is64) {
            const long long* p = (const long long*)ei;
            g_sd[i] = make_int2((int)p[i], (int)p[E + i]);
        } else {
            const int* p = (const int*)ei;
            g_sd[i] = make_int2(p[i], p[E + i]);
        }
    } else {
        g_sd[i] = make_int2(i - E, i - E);
    }
}

// ---------------- GEMM: h = affine(x) @ W^T ----------------
// Fused: BN finalize (prologue, from colsum/colsq), alpha_s/alpha_d epilogue, g_s zeroing.
// 256 threads, block tile M x OUT with M = 4096/OUT; thread tile 4x4 (16 acc regs).
// __launch_bounds__(256, 6) -> ~40 regs -> 6 CTAs/SM (75% occ) vs 3 before.
template <int IN, int OUT>
__global__ void __launch_bounds__(256, 6)
gemm_kernel(const float* __restrict__ x, const float* __restrict__ W,
            const float* __restrict__ gamma, const float* __restrict__ beta,
            const float* __restrict__ colsum, const float* __restrict__ colsq,
            float invn, int useAffine,
            const float* __restrict__ avs, const float* __restrict__ avd,
            float* __restrict__ h, int n) {
    const int M  = 4096 / OUT;         // 64 (OUT=64) or 32 (OUT=128)
    const int OC = OUT / 4;            // col groups: 16 or 32
    const int KC = 32;
    const int SXS = M + 4;
    const int SWS = OUT + 4;

    __shared__ __align__(16) float sSc[IN];
    __shared__ __align__(16) float sSh[IN];
    __shared__ __align__(16) float sX[KC * SXS];
    __shared__ __align__(16) float sW[KC * SWS];

    int tid = threadIdx.x;
    int og = tid % OC;
    int rg = tid / OC;
    int r0 = blockIdx.x * M;

    if (useAffine) {
        for (int o = tid; o < IN; o += 256) {
            float mu = colsum[o] * invn;
            float var = colsq[o] * invn - mu * mu;
            float sc = gamma[o] * rsqrtf(var + 1e-5f);
            sSc[o] = sc;
            sSh[o] = beta[o] - mu * sc;
        }
        __syncthreads();
    }

    float acc[4][4];
#pragma unroll
    for (int i = 0; i < 4; i++)
#pragma unroll
        for (int j = 0; j < 4; j++) acc[i][j] = 0.f;

    for (int kc = 0; kc < IN; kc += KC) {
        // x tile [M x KC] -> sX[k][r] (transposed), optional affine
        for (int idx = tid; idx < M * (KC / 4); idx += 256) {
            int r = idx >> 3, q = idx & 7;
            int k = q * 4;
            int row = r0 + r;
            float4 v = (row < n) ? *(const float4*)&x[row * IN + kc + k]
                                 : make_float4(0.f, 0.f, 0.f, 0.f);
            if (useAffine) {
                v.x = v.x * sSc[kc + k] + sSh[kc + k];
                v.y = v.y * sSc[kc + k + 1] + sSh[kc + k + 1];
                v.z = v.z * sSc[kc + k + 2] + sSh[kc + k + 2];
                v.w = v.w * sSc[kc + k + 3] + sSh[kc + k + 3];
            }
            sX[(k + 0) * SXS + r] = v.x;
            sX[(k + 1) * SXS + r] = v.y;
            sX[(k + 2) * SXS + r] = v.z;
            sX[(k + 3) * SXS + r] = v.w;
        }
        // W tile [OUT x KC] -> sW[k][o] (transposed)
        for (int idx = tid; idx < OUT * (KC / 4); idx += 256) {
            int o = idx >> 3, q = idx & 7;
            int k = q * 4;
            float4 w = *(const float4*)&W[o * IN + kc + k];
            sW[(k + 0) * SWS + o] = w.x;
            sW[(k + 1) * SWS + o] = w.y;
            sW[(k + 2) * SWS + o] = w.z;
            sW[(k + 3) * SWS + o] = w.w;
        }
        __syncthreads();

#pragma unroll
        for (int k = 0; k < KC; k++) {
            float4 a = *(const float4*)&sX[k * SXS + rg * 4];
            float4 b = *(const float4*)&sW[k * SWS + og * 4];
            float av[4] = {a.x, a.y, a.z, a.w};
            float bv[4] = {b.x, b.y, b.z, b.w};
#pragma unroll
            for (int i = 0; i < 4; i++)
#pragma unroll
                for (int j = 0; j < 4; j++)
                    acc[i][j] += av[i] * bv[j];
        }
        __syncthreads();
    }

    // alpha vectors for this thread's 4 columns
    float avsr[4], avdr[4];
#pragma unroll
    for (int j = 0; j < 4; j++) {
        avsr[j] = __ldg(&avs[og * 4 + j]);
        avdr[j] = __ldg(&avd[og * 4 + j]);
    }

    // write h + alpha partials (smem overlay on sX/sW, free after last sync)
    float* sP = sX;                    // [M * OC] = 1024 floats
    float* sQ = sW;                    // [M * OC] = 1024 floats
#pragma unroll
    for (int i = 0; i < 4; i++) {
        int rl = rg * 4 + i;
        int row = r0 + rl;
        float ps = 0.f, pd = 0.f;
#pragma unroll
        for (int j = 0; j < 4; j++) {
            ps += acc[i][j] * avsr[j];
            pd += acc[i][j] * avdr[j];
        }
        sP[rl * OC + og] = ps;
        sQ[rl * OC + og] = pd;
        if (row < n) {
            float4 v = make_float4(acc[i][0], acc[i][1], acc[i][2], acc[i][3]);
            *(float4*)&h[row * OUT + og * 4] = v;
        }
    }
    __syncthreads();
    if (tid < M) {
        int row = r0 + tid;
        if (row < n) {
            float as = 0.f, ad = 0.f;
#pragma unroll
            for (int t = 0; t < OC; t++) {
                as += sP[tid * OC + t];
                ad += sQ[tid * OC + t];
            }
            g_as[row] = as;
            g_ad[row] = ad;
            g_s[row] = 0.f;
        }
    }
}

// ---------------- fused edge pass: t = exp(leaky_relu(as+ad)); segment sum ----------------
__global__ void edge12_kernel(int ET) {
    int i = blockIdx.x * blockDim.x + threadIdx.x;
    if (i >= ET) return;
    int2 sd = g_sd[i];
    float e = g_as[sd.x] + g_ad[sd.y];
    e = (e >= 0.f) ? e : 0.2f * e;
    float t = __expf(e);
    g_e[i] = t;
    atomicAdd(&g_s[sd.y], t);
}

// ---------------- edge pass 3: agg[dst] += alpha * h[src]  (vector red) ----------------
template <int OUT>
__global__ void edge3_kernel(const float* __restrict__ h, int ET) {
    const int G = OUT / 4;
    int gtid = blockIdx.x * blockDim.x + threadIdx.x;
    int i = gtid / G;
    int j = gtid % G;
    if (i >= ET) return;
    int2 sd = g_sd[i];
    float alpha = __fdividef(g_e[i], g_s[sd.y] + 1e-16f);
    const float4 hv = *(const float4*)&h[sd.x * OUT + j * 4];
    float vx = alpha * hv.x, vy = alpha * hv.y, vz = alpha * hv.z, vw = alpha * hv.w;
    float* p = &g_agg[sd.y * OUT + j * 4];
    asm volatile("red.global.add.v4.f32 [%0], {%1, %2, %3, %4};"
                 :: "l"(p), "f"(vx), "f"(vy), "f"(vz), "f"(vw) : "memory");
}

// ---------------- epilogue: y = relu(agg + b), BN stats, re-zero agg ----------------
template <int OUT>
__global__ void epi_bn_kernel(const float* __restrict__ b, float* __restrict__ y,
                              float* __restrict__ colsum, float* __restrict__ colsq, int n) {
    const int T = 256;
    const int RT = T / OUT;
    const int RPB = 64;
    int o = threadIdx.x % OUT;
    int rsub = threadIdx.x / OUT;
    int r0 = blockIdx.x * RPB;
    float bo = b[o];
    float sum = 0.f, sq = 0.f;
    for (int r = rsub; r < RPB; r += RT) {
        int row = r0 + r;
        if (row >= n) break;
        float v = g_agg[row * OUT + o] + bo;
        g_agg[row * OUT + o] = 0.f;                 // restore zero invariant (line is hot)
        v = (v > 0.f) ? v : 0.f;
        y[row * OUT + o] = v;
        sum += v; sq += v * v;
    }
    __shared__ float ssum[T], ssq[T];
    ssum[threadIdx.x] = sum; ssq[threadIdx.x] = sq;
    __syncthreads();
    if (rsub == 0) {
#pragma unroll
        for (int t = 1; t < RT; t++) { sum += ssum[t * OUT + o]; sq += ssq[t * OUT + o]; }
        atomicAdd(&colsum[o], sum);
        atomicAdd(&colsq[o], sq);
    }
}

// ---------------- final: x_hat = relu(agg + b4); out = [|x-x_hat|, x_hat]; re-zero agg ----
__global__ void final_kernel(const float* __restrict__ x, const float* __restrict__ b4,
                             float* __restrict__ out, int n, int out_size) {
    int i = blockIdx.x * blockDim.x + threadIdx.x;
    int total = n * FEAT;
    if (i >= total) return;
    float v = g_agg[i] + b4[i & (FEAT - 1)];
    g_agg[i] = 0.f;                                  // restore zero invariant
    v = (v > 0.f) ? v : 0.f;
    out[i] = fabsf(x[i] - v);
    if (out_size >= 2 * total) out[total + i] = v;
}

extern "C" void kernel_launch(void* const* d_in, const int* in_sizes, int n_in,
                              void* d_out, int out_size) {
    const float* x   = (const float*)d_in[0];
    const void*  ei  = d_in[1];
    const float* W1  = (const float*)d_in[2];
    const float* a1s = (const float*)d_in[3];
    const float* a1d = (const float*)d_in[4];
    const float* b1  = (const float*)d_in[5];
    const float* g1  = (const float*)d_in[6];
    const float* be1 = (const float*)d_in[7];
    const float* W2  = (const float*)d_in[8];
    const float* a2s = (const float*)d_in[9];
    const float* a2d = (const float*)d_in[10];
    const float* b2  = (const float*)d_in[11];
    const float* g2  = (const float*)d_in[12];
    const float* be2 = (const float*)d_in[13];
    const float* W3  = (const float*)d_in[14];
    const float* a3s = (const float*)d_in[15];
    const float* a3d = (const float*)d_in[16];
    const float* b3  = (const float*)d_in[17];
    const float* g3  = (const float*)d_in[18];
    const float* be3 = (const float*)d_in[19];
    const float* W4  = (const float*)d_in[20];
    const float* a4s = (const float*)d_in[21];
    const float* a4d = (const float*)d_in[22];
    const float* b4  = (const float*)d_in[23];

    int n  = in_sizes[0] / FEAT;     // 50000
    int E  = in_sizes[1] / 2;        // 800000
    int ET = E + n;

    float *hbuf, *ybuf, *csum, *csq;
    cudaGetSymbolAddress((void**)&hbuf, g_h);
    cudaGetSymbolAddress((void**)&ybuf, g_y);
    cudaGetSymbolAddress((void**)&csum, g_colsum);
    cudaGetSymbolAddress((void**)&csq,  g_colsq);

    float invn = 1.0f / (float)n;

    start_kernel<<<1, 512>>>(ei);
    convert_kernel<<<(ET + 255) / 256, 256>>>(ei, E, ET);

    // ---- Layer 1: 128 -> 64 ----
    gemm_kernel<FEAT, HID><<<(n + 63) / 64, 256>>>(
        x, W1, nullptr, nullptr, nullptr, nullptr, invn, 0, a1s, a1d, hbuf, n);
    edge12_kernel<<<(ET + 255) / 256, 256>>>(ET);
    edge3_kernel<HID><<<(unsigned)(((long long)ET * (HID / 4) + 255) / 256), 256>>>(hbuf, ET);
    epi_bn_kernel<HID><<<(n + 63) / 64, 256>>>(b1, ybuf, csum + 0 * FEAT, csq + 0 * FEAT, n);

    // ---- Layer 2: 64 -> 64 (BN1 finalize folded into GEMM prologue) ----
    gemm_kernel<HID, HID><<<(n + 63) / 64, 256>>>(
        ybuf, W2, g1, be1, csum + 0 * FEAT, csq + 0 * FEAT, invn, 1, a2s, a2d, hbuf, n);
    edge12_kernel<<<(ET + 255) / 256, 256>>>(ET);
    edge3_kernel<HID><<<(unsigned)(((long long)ET * (HID / 4) + 255) / 256), 256>>>(hbuf, ET);
    epi_bn_kernel<HID><<<(n + 63) / 64, 256>>>(b2, ybuf, csum + 1 * FEAT, csq + 1 * FEAT, n);

    // ---- Layer 3: 64 -> 64 ----
    gemm_kernel<HID, HID><<<(n + 63) / 64, 256>>>(
        ybuf, W3, g2, be2, csum + 1 * FEAT, csq + 1 * FEAT, invn, 1, a3s, a3d, hbuf, n);
    edge12_kernel<<<(ET + 255) / 256, 256>>>(ET);
    edge3_kernel<HID><<<(unsigned)(((long long)ET * (HID / 4) + 255) / 256), 256>>>(hbuf, ET);
    epi_bn_kernel<HID><<<(n + 63) / 64, 256>>>(b3, ybuf, csum + 2 * FEAT, csq + 2 * FEAT, n);

    // ---- Layer 4: 64 -> 128 (no BN after) ----
    gemm_kernel<HID, FEAT><<<(n + 31) / 32, 256>>>(
        ybuf, W4, g3, be3, csum + 2 * FEAT, csq + 2 * FEAT, invn, 1, a4s, a4d, hbuf, n);
    edge12_kernel<<<(ET + 255) / 256, 256>>>(ET);
    edge3_kernel<FEAT><<<(unsigned)(((long long)ET * (FEAT / 4) + 255) / 256), 256>>>(hbuf, ET);
    final_kernel<<<(n * FEAT + 255) / 256, 256>>>(x, b4, (float*)d_out, n, out_size);
}